// round 5
// baseline (speedup 1.0000x reference)
#include <cuda_runtime.h>

// Problem constants (fixed shapes for this dataset)
#define Nn 50000
#define Ee 600000

typedef unsigned long long u64;

// ---------------- scratch (static __device__ — no allocation allowed) ----------------
__device__ int      g_is64;
__device__ int      g_src[Ee];
__device__ int      g_dst[Ee];
__device__ float    g_escale[Ee];
__device__ float    g_e256[(size_t)Ee * 256];   // KV (stage A) then M1 (stage B)
__device__ float    g_scores[(size_t)Ee * 4];
__device__ unsigned g_smax[Nn * 4];
__device__ float    g_ssum[Nn * 4];
__device__ float    g_Qn[Nn * 128];
__device__ float    g_XKV[Nn * 256];
__device__ float    g_agg[Nn * 128];
__device__ float    g_agg2[Nn * 128];
__device__ float    g_tmp[Nn * 128];
__device__ float    g_h[Nn * 128];
__device__ float    g_h2[Nn * 128];
__device__ float    g_hn[Nn * 128];
__device__ float    g_hff[Nn * 128];
__device__ float    g_G[Nn * 128];
__device__ float    g_Hd[Nn * 256];
__device__ float    g_Hs[Nn * 256];
__device__ float    g_cat[Nn * 256];
__device__ float    g_GU[Nn * 256];
__device__ float    g_cat2[Nn * 256];
__device__ float    g_F1[Nn * 512];
__device__ float    g_Wkv[128 * 256];
__device__ float    g_bkv[256];
__device__ float    g_Wgu[256 * 256];
__device__ float    g_bgu[256];

// ---------------- helpers ----------------
__device__ __forceinline__ float warp_sum32(float v) {
#pragma unroll
    for (int o = 16; o; o >>= 1) v += __shfl_xor_sync(0xffffffffu, v, o);
    return v;
}
__device__ __forceinline__ float gelu_f(float x) {
    return 0.5f * x * (1.0f + erff(x * 0.7071067811865476f));
}
__device__ __forceinline__ float sigm_f(float x) { return 1.0f / (1.0f + expf(-x)); }
__device__ __forceinline__ unsigned fenc(float f) {
    unsigned u = __float_as_uint(f);
    return (u & 0x80000000u) ? ~u : (u | 0x80000000u);
}
__device__ __forceinline__ float fdec(unsigned e) {
    unsigned u = (e & 0x80000000u) ? (e & 0x7fffffffu) : ~e;
    return __uint_as_float(u);
}
// packed 2x fp32 FMA (Blackwell FFMA2) — bit-exact per-element fp32 fma
__device__ __forceinline__ u64 fma2(u64 a, u64 b, u64 c) {
    u64 d;
    asm("fma.rn.f32x2 %0, %1, %2, %3;" : "=l"(d) : "l"(a), "l"(b), "l"(c));
    return d;
}
__device__ __forceinline__ float2 u2f2(u64 v) {
    float2 f;
    asm("mov.b64 {%0, %1}, %2;" : "=f"(f.x), "=f"(f.y) : "l"(v));
    return f;
}

// ---------------- 128x128x8 register-tiled fp32 GEMM, f32x2 packed FMA ----------------
// C[M,N] = A[M,K] @ W[K,N] (+bias) (+activation/fusion)
// EPI: 0=store, 1=gelu store, 2=sigmoid store,
//      3=scatter-atomicAdd to C[idxD[row]] scaled by sscale[row]
//      4=add t1[idxS[row]] then store  (KV fusion: + XKV[src])
//      5=gelu(acc + bias + t1[idxD[row]] + t2[idxS[row]]) store  (M1 fusion)
template <int EPI>
__global__ void __launch_bounds__(256) gemm_k(
    const float* __restrict__ A, const float* __restrict__ W,
    const float* __restrict__ bias, float* __restrict__ C,
    int M, int K, int Ncols,
    const int* __restrict__ idxD, const int* __restrict__ idxS,
    const float* __restrict__ t1, const float* __restrict__ t2,
    const float* __restrict__ sscale)
{
    __shared__ float As2[8][264];  // [k][2*m] duplicated pairs (a,a); broadcast reads
    __shared__ float Bs[8][132];   // [k][n], padded
    const int bm = blockIdx.x * 128;
    const int bn = blockIdx.y * 128;
    const int tid = threadIdx.x;
    const int ty = tid >> 4;           // 0..15 -> rows ty*8
    const int tx = tid & 15;           // 0..15 -> cols tx*8
    const int la_r = tid >> 1;         // A load: row within tile
    const int la_k = (tid & 1) << 2;   // A load: k offset (0 or 4)
    const int lb_k = tid >> 5;         // B load: k row
    const int lb_c = (tid & 31) << 2;  // B load: col offset

    u64 acc2[8][4];
#pragma unroll
    for (int i = 0; i < 8; i++)
#pragma unroll
        for (int j = 0; j < 4; j++) acc2[i][j] = 0ull;

    const int arow = bm + la_r;
    const bool aok = arow < M;
    const float* Aptr = A + (size_t)arow * K + la_k;
    const float* Wptr = W + (size_t)lb_k * Ncols + bn + lb_c;

    for (int k0 = 0; k0 < K; k0 += 8) {
        float4 av = make_float4(0.f, 0.f, 0.f, 0.f);
        if (aok) av = *reinterpret_cast<const float4*>(Aptr + k0);
        float4 bv = *reinterpret_cast<const float4*>(Wptr + (size_t)k0 * Ncols);
        __syncthreads();
        *reinterpret_cast<float2*>(&As2[la_k + 0][2 * la_r]) = make_float2(av.x, av.x);
        *reinterpret_cast<float2*>(&As2[la_k + 1][2 * la_r]) = make_float2(av.y, av.y);
        *reinterpret_cast<float2*>(&As2[la_k + 2][2 * la_r]) = make_float2(av.z, av.z);
        *reinterpret_cast<float2*>(&As2[la_k + 3][2 * la_r]) = make_float2(av.w, av.w);
        *reinterpret_cast<float4*>(&Bs[lb_k][lb_c]) = bv;
        __syncthreads();
#pragma unroll
        for (int kk = 0; kk < 8; kk++) {
            const u64* ar = reinterpret_cast<const u64*>(&As2[kk][ty * 16]);
            const u64* br = reinterpret_cast<const u64*>(&Bs[kk][tx * 8]);
            u64 ap[8], bp[4];
#pragma unroll
            for (int i = 0; i < 8; i++) ap[i] = ar[i];
#pragma unroll
            for (int j = 0; j < 4; j++) bp[j] = br[j];
#pragma unroll
            for (int i = 0; i < 8; i++)
#pragma unroll
                for (int j = 0; j < 4; j++)
                    acc2[i][j] = fma2(ap[i], bp[j], acc2[i][j]);
        }
    }

    float bj[8];
    if (bias) {
        *(float4*)(bj)     = *(const float4*)(bias + bn + tx * 8);
        *(float4*)(bj + 4) = *(const float4*)(bias + bn + tx * 8 + 4);
    } else {
#pragma unroll
        for (int j = 0; j < 8; j++) bj[j] = 0.f;
    }
#pragma unroll
    for (int i = 0; i < 8; i++) {
        int row = bm + ty * 8 + i;
        if (row >= M) continue;
        float v[8];
#pragma unroll
        for (int j = 0; j < 4; j++) {
            float2 f = u2f2(acc2[i][j]);
            v[2 * j]     = f.x + bj[2 * j];
            v[2 * j + 1] = f.y + bj[2 * j + 1];
        }
        if (EPI == 1) {
#pragma unroll
            for (int j = 0; j < 8; j++) v[j] = gelu_f(v[j]);
        }
        if (EPI == 2) {
#pragma unroll
            for (int j = 0; j < 8; j++) v[j] = sigm_f(v[j]);
        }
        if (EPI == 4) {
            const float* g = t1 + (size_t)idxS[row] * Ncols + bn + tx * 8;
            float4 g0 = *(const float4*)g;
            float4 g1 = *(const float4*)(g + 4);
            v[0] += g0.x; v[1] += g0.y; v[2] += g0.z; v[3] += g0.w;
            v[4] += g1.x; v[5] += g1.y; v[6] += g1.z; v[7] += g1.w;
        }
        if (EPI == 5) {
            const float* gd = t1 + (size_t)idxD[row] * Ncols + bn + tx * 8;
            const float* gs = t2 + (size_t)idxS[row] * Ncols + bn + tx * 8;
            float4 d0 = *(const float4*)gd;
            float4 d1 = *(const float4*)(gd + 4);
            float4 s0 = *(const float4*)gs;
            float4 s1 = *(const float4*)(gs + 4);
            v[0] = gelu_f(v[0] + d0.x + s0.x);
            v[1] = gelu_f(v[1] + d0.y + s0.y);
            v[2] = gelu_f(v[2] + d0.z + s0.z);
            v[3] = gelu_f(v[3] + d0.w + s0.w);
            v[4] = gelu_f(v[4] + d1.x + s1.x);
            v[5] = gelu_f(v[5] + d1.y + s1.y);
            v[6] = gelu_f(v[6] + d1.z + s1.z);
            v[7] = gelu_f(v[7] + d1.w + s1.w);
        }
        if (EPI == 3) {
            int node = idxD[row];
            float sc = sscale[row];
            float* dp = C + (size_t)node * Ncols + bn + tx * 8;
#pragma unroll
            for (int j = 0; j < 8; j++) atomicAdd(dp + j, v[j] * sc);
        } else {
            float* cp = C + (size_t)row * Ncols + bn + tx * 8;
            *(float4*)cp       = *(float4*)(v);
            *(float4*)(cp + 4) = *(float4*)(v + 4);
        }
    }
}

// ---------------- small kernels ----------------
__global__ void k_detect(const void* ei) {
    if (blockIdx.x == 0 && threadIdx.x == 0) {
        const long long* p = (const long long*)ei;
        int ok = 1;
        for (int i = 0; i < 64; i++) {
            long long v = p[i];
            if (v < 0 || v >= (long long)Nn) { ok = 0; break; }
        }
        g_is64 = ok;
    }
}

__global__ void k_convert(const void* ei) {
    int i = blockIdx.x * blockDim.x + threadIdx.x;
    if (i >= Ee) return;
    if (g_is64) {
        const long long* p = (const long long*)ei;
        g_src[i] = (int)p[i];
        g_dst[i] = (int)p[Ee + i];
    } else {
        const int* p = (const int*)ei;
        g_src[i] = p[i];
        g_dst[i] = p[Ee + i];
    }
}

__global__ void k_escale(const float* __restrict__ qd, const float* __restrict__ wd,
                         const float* __restrict__ bd) {
    int e = blockIdx.x * blockDim.x + threadIdx.x;
    if (e >= Ee) return;
    float q = qd[e];
    float s = 0.f;
#pragma unroll
    for (int h = 0; h < 4; h++) s += sigm_f(q * wd[h] + bd[h]);
    g_escale[e] = 1.f + 0.25f * s;
}

__global__ void k_zero(float* p, int n) {
    int i = blockIdx.x * blockDim.x + threadIdx.x;
    if (i < n) p[i] = 0.f;
}
__global__ void k_fillu(unsigned* p, int n, unsigned v) {
    int i = blockIdx.x * blockDim.x + threadIdx.x;
    if (i < n) p[i] = v;
}

__global__ void k_pack2(const float* __restrict__ A, const float* __restrict__ B,
                        float* __restrict__ out, int K, int nA, int nB) {
    int i = blockIdx.x * blockDim.x + threadIdx.x;
    int Wt = nA + nB;
    if (i >= K * Wt) return;
    int k = i / Wt, j = i - k * Wt;
    out[i] = (j < nA) ? A[k * nA + j] : B[k * nB + (j - nA)];
}

// one warp per edge: per-head q.k + tanh temporal bias; atomicMax segment max
__global__ void k_scores(const float* __restrict__ tp, const float* __restrict__ wt,
                         const float* __restrict__ bt) {
    int e = blockIdx.x * 8 + (threadIdx.x >> 5);
    if (e >= Ee) return;
    int lane = threadIdx.x & 31;
    int h = lane >> 3, j = lane & 7;
    int dst = g_dst[e];
    float4 q = *(const float4*)(g_Qn + (size_t)dst * 128 + h * 32 + j * 4);
    float4 k = *(const float4*)(g_e256 + (size_t)e * 256 + h * 32 + j * 4);
    float d = q.x * k.x + q.y * k.y + q.z * k.z + q.w * k.w;
    d += __shfl_xor_sync(0xffffffffu, d, 1);
    d += __shfl_xor_sync(0xffffffffu, d, 2);
    d += __shfl_xor_sync(0xffffffffu, d, 4);
    if (j == 0) {
        float s = d * 0.17677669529663687f + tanhf(tp[e] * wt[h] + bt[h]);
        g_scores[(size_t)e * 4 + h] = s;
        atomicMax(&g_smax[dst * 4 + h], fenc(s));
    }
}

__global__ void k_expsum() {
    int i = blockIdx.x * blockDim.x + threadIdx.x;
    if (i >= Ee * 4) return;
    int e = i >> 2, h = i & 3;
    int dst = g_dst[e];
    float mx = fdec(g_smax[dst * 4 + h]);
    float ex = expf(g_scores[i] - mx);
    g_scores[i] = ex;
    atomicAdd(&g_ssum[dst * 4 + h], ex);
}

// one warp per edge: msg = attn*v, scatter-add into agg
__global__ void k_message() {
    int e = blockIdx.x * 8 + (threadIdx.x >> 5);
    if (e >= Ee) return;
    int lane = threadIdx.x & 31;
    int h = lane >> 3, j = lane & 7;
    int dst = g_dst[e];
    float attn = g_scores[(size_t)e * 4 + h] / g_ssum[dst * 4 + h];
    float4 v = *(const float4*)(g_e256 + (size_t)e * 256 + 128 + h * 32 + j * 4);
    float* o = g_agg + (size_t)dst * 128 + h * 32 + j * 4;
    atomicAdd(o + 0, attn * v.x);
    atomicAdd(o + 1, attn * v.y);
    atomicAdd(o + 2, attn * v.z);
    atomicAdd(o + 3, attn * v.w);
}

// out = LN(a + b), one warp per 128-wide row
__global__ void k_ln_add(const float* __restrict__ a, const float* __restrict__ b,
                         float* __restrict__ out) {
    int n = blockIdx.x * 8 + (threadIdx.x >> 5);
    if (n >= Nn) return;
    int lane = threadIdx.x & 31;
    float4 va = ((const float4*)a)[(size_t)n * 32 + lane];
    float4 vb = ((const float4*)b)[(size_t)n * 32 + lane];
    float4 p = make_float4(va.x + vb.x, va.y + vb.y, va.z + vb.z, va.w + vb.w);
    float s = warp_sum32(p.x + p.y + p.z + p.w);
    float sq = warp_sum32(p.x * p.x + p.y * p.y + p.z * p.z + p.w * p.w);
    float m = s * (1.f / 128.f);
    float var = sq * (1.f / 128.f) - m * m;
    float inv = rsqrtf(var + 1e-5f);
    float4 r = make_float4((p.x - m) * inv, (p.y - m) * inv, (p.z - m) * inv, (p.w - m) * inv);
    ((float4*)out)[(size_t)n * 32 + lane] = r;
}

// out[N,256] = [a | b]
__global__ void k_concat(const float* __restrict__ a, const float* __restrict__ b,
                         float* __restrict__ out) {
    int i = blockIdx.x * blockDim.x + threadIdx.x;
    if (i >= Nn * 64) return;
    int n = i >> 6, c = i & 63;
    float4 v = (c < 32) ? ((const float4*)a)[(size_t)n * 32 + c]
                        : ((const float4*)b)[(size_t)n * 32 + (c - 32)];
    ((float4*)out)[(size_t)i] = v;
}

// stage-B combine: g=sigmoid(GU[:,:128]), u=gelu(GU[:,128:]); h2=LN(h*(1-g)+u*g); hn=LN(h2)
__global__ void k_combine() {
    int n = blockIdx.x * 8 + (threadIdx.x >> 5);
    if (n >= Nn) return;
    int lane = threadIdx.x & 31;
    const float4* GU4 = (const float4*)g_GU;
    float4 gv = GU4[(size_t)n * 64 + lane];
    float4 uv = GU4[(size_t)n * 64 + 32 + lane];
    float4 hv = ((const float4*)g_h)[(size_t)n * 32 + lane];
    float gx = sigm_f(gv.x), gy = sigm_f(gv.y), gz = sigm_f(gv.z), gw = sigm_f(gv.w);
    float ux = gelu_f(uv.x), uy = gelu_f(uv.y), uz = gelu_f(uv.z), uw = gelu_f(uv.w);
    float4 p;
    p.x = hv.x * (1.f - gx) + ux * gx;
    p.y = hv.y * (1.f - gy) + uy * gy;
    p.z = hv.z * (1.f - gz) + uz * gz;
    p.w = hv.w * (1.f - gw) + uw * gw;
    float s = warp_sum32(p.x + p.y + p.z + p.w);
    float sq = warp_sum32(p.x * p.x + p.y * p.y + p.z * p.z + p.w * p.w);
    float m = s * (1.f / 128.f);
    float var = sq * (1.f / 128.f) - m * m;
    float inv = rsqrtf(var + 1e-5f);
    float4 h2 = make_float4((p.x - m) * inv, (p.y - m) * inv, (p.z - m) * inv, (p.w - m) * inv);
    ((float4*)g_h2)[(size_t)n * 32 + lane] = h2;
    float s2 = warp_sum32(h2.x + h2.y + h2.z + h2.w);
    float sq2 = warp_sum32(h2.x * h2.x + h2.y * h2.y + h2.z * h2.z + h2.w * h2.w);
    float m2 = s2 * (1.f / 128.f);
    float var2 = sq2 * (1.f / 128.f) - m2 * m2;
    float inv2 = rsqrtf(var2 + 1e-5f);
    float4 hn = make_float4((h2.x - m2) * inv2, (h2.y - m2) * inv2,
                            (h2.z - m2) * inv2, (h2.w - m2) * inv2);
    ((float4*)g_hn)[(size_t)n * 32 + lane] = hn;
}

// out = LN(h2 + G*hff)
__global__ void k_final(float* __restrict__ out) {
    int n = blockIdx.x * 8 + (threadIdx.x >> 5);
    if (n >= Nn) return;
    int lane = threadIdx.x & 31;
    float4 a = ((const float4*)g_h2)[(size_t)n * 32 + lane];
    float4 g = ((const float4*)g_G)[(size_t)n * 32 + lane];
    float4 f = ((const float4*)g_hff)[(size_t)n * 32 + lane];
    float4 p = make_float4(a.x + g.x * f.x, a.y + g.y * f.y, a.z + g.z * f.z, a.w + g.w * f.w);
    float s = warp_sum32(p.x + p.y + p.z + p.w);
    float sq = warp_sum32(p.x * p.x + p.y * p.y + p.z * p.z + p.w * p.w);
    float m = s * (1.f / 128.f);
    float var = sq * (1.f / 128.f) - m * m;
    float inv = rsqrtf(var + 1e-5f);
    float4 r = make_float4((p.x - m) * inv, (p.y - m) * inv, (p.z - m) * inv, (p.w - m) * inv);
    ((float4*)out)[(size_t)n * 32 + lane] = r;
}

// ---------------- launch ----------------
static inline int cdiv_i(int a, int b) { return (a + b - 1) / b; }

extern "C" void kernel_launch(void* const* d_in, const int* in_sizes, int n_in,
                              void* d_out, int out_size) {
    (void)in_sizes; (void)n_in; (void)out_size;
    const float* x    = (const float*)d_in[0];
    const void*  ei   = d_in[1];
    const float* ge   = (const float*)d_in[2];
    const float* tp   = (const float*)d_in[3];
    const float* qd   = (const float*)d_in[4];
    const float* Wq   = (const float*)d_in[5];  const float* bq   = (const float*)d_in[6];
    const float* Wk   = (const float*)d_in[7];  const float* bk   = (const float*)d_in[8];
    const float* Wv   = (const float*)d_in[9];  const float* bv   = (const float*)d_in[10];
    const float* wt   = (const float*)d_in[11]; const float* bt   = (const float*)d_in[12];
    const float* Wo   = (const float*)d_in[13]; const float* bo   = (const float*)d_in[14];
    const float* Wm1  = (const float*)d_in[15]; const float* bm1  = (const float*)d_in[16];
    const float* Wm2  = (const float*)d_in[17]; const float* bm2  = (const float*)d_in[18];
    const float* wd   = (const float*)d_in[19]; const float* bd   = (const float*)d_in[20];
    const float* Wg   = (const float*)d_in[21]; const float* bg   = (const float*)d_in[22];
    const float* Wu   = (const float*)d_in[23]; const float* bu   = (const float*)d_in[24];
    const float* Wf1  = (const float*)d_in[25]; const float* bf1  = (const float*)d_in[26];
    const float* Wf2  = (const float*)d_in[27]; const float* bf2  = (const float*)d_in[28];
    const float* Wgate= (const float*)d_in[29]; const float* bgate= (const float*)d_in[30];

    void* pv;
    float *p_Qn, *p_XKV, *p_e256, *p_agg, *p_agg2, *p_tmp, *p_h, *p_h2, *p_hn, *p_hff, *p_G;
    float *p_Hd, *p_Hs, *p_cat, *p_GU, *p_cat2, *p_F1, *p_Wkv, *p_bkv, *p_Wgu, *p_bgu, *p_ssum, *p_escale;
    unsigned* p_smax; int* p_dst; int* p_src;
    cudaGetSymbolAddress(&pv, g_Qn);     p_Qn    = (float*)pv;
    cudaGetSymbolAddress(&pv, g_XKV);    p_XKV   = (float*)pv;
    cudaGetSymbolAddress(&pv, g_e256);   p_e256  = (float*)pv;
    cudaGetSymbolAddress(&pv, g_agg);    p_agg   = (float*)pv;
    cudaGetSymbolAddress(&pv, g_agg2);   p_agg2  = (float*)pv;
    cudaGetSymbolAddress(&pv, g_tmp);    p_tmp   = (float*)pv;
    cudaGetSymbolAddress(&pv, g_h);      p_h     = (float*)pv;
    cudaGetSymbolAddress(&pv, g_h2);     p_h2    = (float*)pv;
    cudaGetSymbolAddress(&pv, g_hn);     p_hn    = (float*)pv;
    cudaGetSymbolAddress(&pv, g_hff);    p_hff   = (float*)pv;
    cudaGetSymbolAddress(&pv, g_G);      p_G     = (float*)pv;
    cudaGetSymbolAddress(&pv, g_Hd);     p_Hd    = (float*)pv;
    cudaGetSymbolAddress(&pv, g_Hs);     p_Hs    = (float*)pv;
    cudaGetSymbolAddress(&pv, g_cat);    p_cat   = (float*)pv;
    cudaGetSymbolAddress(&pv, g_GU);     p_GU    = (float*)pv;
    cudaGetSymbolAddress(&pv, g_cat2);   p_cat2  = (float*)pv;
    cudaGetSymbolAddress(&pv, g_F1);     p_F1    = (float*)pv;
    cudaGetSymbolAddress(&pv, g_Wkv);    p_Wkv   = (float*)pv;
    cudaGetSymbolAddress(&pv, g_bkv);    p_bkv   = (float*)pv;
    cudaGetSymbolAddress(&pv, g_Wgu);    p_Wgu   = (float*)pv;
    cudaGetSymbolAddress(&pv, g_bgu);    p_bgu   = (float*)pv;
    cudaGetSymbolAddress(&pv, g_ssum);   p_ssum  = (float*)pv;
    cudaGetSymbolAddress(&pv, g_escale); p_escale= (float*)pv;
    cudaGetSymbolAddress(&pv, g_smax);   p_smax  = (unsigned*)pv;
    cudaGetSymbolAddress(&pv, g_dst);    p_dst   = (int*)pv;
    cudaGetSymbolAddress(&pv, g_src);    p_src   = (int*)pv;

    const int TB = 256;

    // --- prep ---
    k_detect<<<1, 1>>>(ei);
    k_convert<<<cdiv_i(Ee, TB), TB>>>(ei);
    k_escale<<<cdiv_i(Ee, TB), TB>>>(qd, wd, bd);
    k_zero<<<cdiv_i(Nn * 128, TB), TB>>>(p_agg, Nn * 128);
    k_zero<<<cdiv_i(Nn * 128, TB), TB>>>(p_agg2, Nn * 128);
    k_zero<<<cdiv_i(Nn * 4, TB), TB>>>(p_ssum, Nn * 4);
    k_fillu<<<cdiv_i(Nn * 4, TB), TB>>>(p_smax, Nn * 4, 0x007FFFFFu);  // enc(-inf)
    k_pack2<<<cdiv_i(128 * 256, TB), TB>>>(Wk, Wv, p_Wkv, 128, 128, 128);
    k_pack2<<<cdiv_i(256, TB), TB>>>(bk, bv, p_bkv, 1, 128, 128);
    k_pack2<<<cdiv_i(256 * 256, TB), TB>>>(Wg, Wu, p_Wgu, 256, 128, 128);
    k_pack2<<<cdiv_i(256, TB), TB>>>(bg, bu, p_bgu, 1, 128, 128);

    // --- stage A: causal temporal attention ---
    gemm_k<0><<<dim3(cdiv_i(Nn, 128), 1), 256>>>(x, Wq, bq, p_Qn, Nn, 128, 128,
        nullptr, nullptr, nullptr, nullptr, nullptr);
    gemm_k<0><<<dim3(cdiv_i(Nn, 128), 2), 256>>>(x, p_Wkv, p_bkv, p_XKV, Nn, 128, 256,
        nullptr, nullptr, nullptr, nullptr, nullptr);
    // KV = ge@Wkv + XKV[src]   (fused gather-add epilogue)
    gemm_k<4><<<dim3(cdiv_i(Ee, 128), 2), 256>>>(ge, p_Wkv, nullptr, p_e256, Ee, 128, 256,
        nullptr, p_src, p_XKV, nullptr, nullptr);
    k_scores<<<cdiv_i(Ee, 8), 256>>>(tp, wt, bt);
    k_expsum<<<cdiv_i(Ee * 4, TB), TB>>>();
    k_message<<<cdiv_i(Ee, 8), 256>>>();
    gemm_k<0><<<dim3(cdiv_i(Nn, 128), 1), 256>>>(p_agg, Wo, bo, p_tmp, Nn, 128, 128,
        nullptr, nullptr, nullptr, nullptr, nullptr);
    k_ln_add<<<cdiv_i(Nn, 8), 256>>>(x, p_tmp, p_h);

    // --- stage B: entanglement-aware conv ---
    gemm_k<0><<<dim3(cdiv_i(Nn, 128), 2), 256>>>(p_h, Wm1, nullptr, p_Hd, Nn, 128, 256,
        nullptr, nullptr, nullptr, nullptr, nullptr);
    gemm_k<0><<<dim3(cdiv_i(Nn, 128), 2), 256>>>(p_h, Wm1 + 128 * 256, nullptr, p_Hs, Nn, 128, 256,
        nullptr, nullptr, nullptr, nullptr, nullptr);
    // M1 = gelu(ge@Wm1g + Hd[dst] + Hs[src] + bm1)   (fused epilogue)
    gemm_k<5><<<dim3(cdiv_i(Ee, 128), 2), 256>>>(ge, Wm1 + 256 * 256, bm1, p_e256, Ee, 128, 256,
        p_dst, p_src, p_Hd, p_Hs, nullptr);
    gemm_k<3><<<dim3(cdiv_i(Ee, 128), 1), 256>>>(p_e256, Wm2, bm2, p_agg2, Ee, 256, 128,
        p_dst, nullptr, nullptr, nullptr, p_escale);
    k_concat<<<cdiv_i(Nn * 64, TB), TB>>>(p_h, p_agg2, p_cat);
    gemm_k<0><<<dim3(cdiv_i(Nn, 128), 2), 256>>>(p_cat, p_Wgu, p_bgu, p_GU, Nn, 256, 256,
        nullptr, nullptr, nullptr, nullptr, nullptr);
    k_combine<<<cdiv_i(Nn, 8), 256>>>();

    // --- stage C: FF + gated residual ---
    gemm_k<1><<<dim3(cdiv_i(Nn, 128), 4), 256>>>(p_hn, Wf1, bf1, p_F1, Nn, 128, 512,
        nullptr, nullptr, nullptr, nullptr, nullptr);
    gemm_k<0><<<dim3(cdiv_i(Nn, 128), 1), 256>>>(p_F1, Wf2, bf2, p_hff, Nn, 512, 128,
        nullptr, nullptr, nullptr, nullptr, nullptr);
    k_concat<<<cdiv_i(Nn * 64, TB), TB>>>(p_h2, p_hff, p_cat2);
    gemm_k<2><<<dim3(cdiv_i(Nn, 128), 1), 256>>>(p_cat2, Wgate, bgate, p_G, Nn, 256, 128,
        nullptr, nullptr, nullptr, nullptr, nullptr);
    k_final<<<cdiv_i(Nn, 8), 256>>>((float*)d_out);
}

// round 6
// speedup vs baseline: 1.2243x; 1.2243x over previous
#include <cuda_runtime.h>

// Problem constants (fixed shapes for this dataset)
#define Nn 50000
#define Ee 600000

// ---------------- scratch (static __device__ — no allocation allowed) ----------------
__device__ int      g_is64;
__device__ int      g_src[Ee];
__device__ int      g_dst[Ee];
__device__ float    g_escale[Ee];
__device__ float    g_e256[(size_t)Ee * 256];   // KV (stage A) then M1 (stage B)
__device__ float    g_scores[(size_t)Ee * 4];
__device__ unsigned g_smax[Nn * 4];
__device__ float    g_ssum[Nn * 4];
__device__ float    g_Qn[Nn * 128];
__device__ float    g_XKV[Nn * 256];
__device__ float    g_agg[Nn * 128];
__device__ float    g_agg2[Nn * 128];
__device__ float    g_tmp[Nn * 128];
__device__ float    g_h[Nn * 128];
__device__ float    g_h2[Nn * 128];
__device__ float    g_hn[Nn * 128];
__device__ float    g_hff[Nn * 128];
__device__ float    g_G[Nn * 128];
__device__ float    g_Hd[Nn * 256];
__device__ float    g_Hs[Nn * 256];
__device__ float    g_GU[Nn * 256];
__device__ float    g_F1[Nn * 512];
__device__ float    g_Wkv[128 * 256];
__device__ float    g_bkv[256];
__device__ float    g_Wgu[256 * 256];
__device__ float    g_bgu[256];

// ---------------- helpers ----------------
__device__ __forceinline__ float warp_sum32(float v) {
#pragma unroll
    for (int o = 16; o; o >>= 1) v += __shfl_xor_sync(0xffffffffu, v, o);
    return v;
}
__device__ __forceinline__ float gelu_f(float x) {
    return 0.5f * x * (1.0f + erff(x * 0.7071067811865476f));
}
__device__ __forceinline__ float sigm_f(float x) { return 1.0f / (1.0f + expf(-x)); }
__device__ __forceinline__ unsigned fenc(float f) {
    unsigned u = __float_as_uint(f);
    return (u & 0x80000000u) ? ~u : (u | 0x80000000u);
}
__device__ __forceinline__ float fdec(unsigned e) {
    unsigned u = (e & 0x80000000u) ? (e & 0x7fffffffu) : ~e;
    return __uint_as_float(u);
}
// vectorized fire-and-forget global float reduction (sm_90+)
__device__ __forceinline__ void red_add_v4(float* p, float a, float b, float c, float d) {
    asm volatile("red.global.add.v4.f32 [%0], {%1, %2, %3, %4};"
                 :: "l"(p), "f"(a), "f"(b), "f"(c), "f"(d) : "memory");
}

// ---------------- generic 128x128x8 register-tiled fp32 GEMM ----------------
// C[M,Ncols] = A[M,K] @ W[K,Ncols] (+bias) (+activation/fusion)
// If ASPLIT: A columns [0,128) come from A, [128,256) from A2 (both row-stride 128).
// EPI: 0=store, 1=gelu store, 2=sigmoid store,
//      3=scatter red.add.v4 to C[idxD[row]] scaled by sscale[row]
//      4=add t1[idxS[row]] then store  (KV fusion: + XKV[src])
//      5=gelu(acc + bias + t1[idxD[row]] + t2[idxS[row]]) store  (M1 fusion)
template <int EPI, bool ASPLIT>
__global__ void __launch_bounds__(256) gemm_k(
    const float* __restrict__ A, const float* __restrict__ A2,
    const float* __restrict__ W,
    const float* __restrict__ bias, float* __restrict__ C,
    int M, int K, int Ncols,
    const int* __restrict__ idxD, const int* __restrict__ idxS,
    const float* __restrict__ t1, const float* __restrict__ t2,
    const float* __restrict__ sscale)
{
    __shared__ float As[8][132];  // [k][m], padded
    __shared__ float Bs[8][132];  // [k][n], padded
    const int bm = blockIdx.x * 128;
    const int bn = blockIdx.y * 128;
    const int tid = threadIdx.x;
    const int ty = tid >> 4;           // 0..15 -> rows ty*8
    const int tx = tid & 15;           // 0..15 -> cols tx*8
    const int la_r = tid >> 1;         // A load: row within tile
    const int la_k = (tid & 1) << 2;   // A load: k offset (0 or 4)
    const int lb_k = tid >> 5;         // B load: k row
    const int lb_c = (tid & 31) << 4;  // B load: col offset (x4 floats)

    float acc[8][8];
#pragma unroll
    for (int i = 0; i < 8; i++)
#pragma unroll
        for (int j = 0; j < 8; j++) acc[i][j] = 0.f;

    const int arow = bm + la_r;
    const bool aok = arow < M;
    const float* Aptr  = A  + (size_t)arow * (ASPLIT ? 128 : K) + la_k;
    const float* Aptr2 = ASPLIT ? (A2 + (size_t)arow * 128 + la_k) : nullptr;
    const float* Wptr = W + (size_t)lb_k * Ncols + bn + ((tid & 31) << 2);

    for (int k0 = 0; k0 < K; k0 += 8) {
        float4 av = make_float4(0.f, 0.f, 0.f, 0.f);
        if (aok) {
            if (ASPLIT) {
                av = (k0 + la_k < 128)
                   ? *reinterpret_cast<const float4*>(Aptr + k0)
                   : *reinterpret_cast<const float4*>(Aptr2 + (k0 - 128));
            } else {
                av = *reinterpret_cast<const float4*>(Aptr + k0);
            }
        }
        float4 bv = *reinterpret_cast<const float4*>(Wptr + (size_t)k0 * Ncols);
        __syncthreads();
        As[la_k + 0][la_r] = av.x;
        As[la_k + 1][la_r] = av.y;
        As[la_k + 2][la_r] = av.z;
        As[la_k + 3][la_r] = av.w;
        *reinterpret_cast<float4*>(&Bs[lb_k][(tid & 31) << 2]) = bv;
        __syncthreads();
#pragma unroll
        for (int kk = 0; kk < 8; kk++) {
            float a0[8], b0[8];
            *(float4*)(a0)     = *(const float4*)(&As[kk][ty * 8]);
            *(float4*)(a0 + 4) = *(const float4*)(&As[kk][ty * 8 + 4]);
            *(float4*)(b0)     = *(const float4*)(&Bs[kk][tx * 8]);
            *(float4*)(b0 + 4) = *(const float4*)(&Bs[kk][tx * 8 + 4]);
#pragma unroll
            for (int i = 0; i < 8; i++)
#pragma unroll
                for (int j = 0; j < 8; j++)
                    acc[i][j] = fmaf(a0[i], b0[j], acc[i][j]);
        }
    }

    float bj[8];
    if (bias) {
        *(float4*)(bj)     = *(const float4*)(bias + bn + tx * 8);
        *(float4*)(bj + 4) = *(const float4*)(bias + bn + tx * 8 + 4);
    } else {
#pragma unroll
        for (int j = 0; j < 8; j++) bj[j] = 0.f;
    }
#pragma unroll
    for (int i = 0; i < 8; i++) {
        int row = bm + ty * 8 + i;
        if (row >= M) continue;
        float v[8];
#pragma unroll
        for (int j = 0; j < 8; j++) v[j] = acc[i][j] + bj[j];
        if (EPI == 1) {
#pragma unroll
            for (int j = 0; j < 8; j++) v[j] = gelu_f(v[j]);
        }
        if (EPI == 2) {
#pragma unroll
            for (int j = 0; j < 8; j++) v[j] = sigm_f(v[j]);
        }
        if (EPI == 4) {
            const float* g = t1 + (size_t)idxS[row] * Ncols + bn + tx * 8;
            float4 g0 = *(const float4*)g;
            float4 g1 = *(const float4*)(g + 4);
            v[0] += g0.x; v[1] += g0.y; v[2] += g0.z; v[3] += g0.w;
            v[4] += g1.x; v[5] += g1.y; v[6] += g1.z; v[7] += g1.w;
        }
        if (EPI == 5) {
            const float* gd = t1 + (size_t)idxD[row] * Ncols + bn + tx * 8;
            const float* gs = t2 + (size_t)idxS[row] * Ncols + bn + tx * 8;
            float4 d0 = *(const float4*)gd;
            float4 d1 = *(const float4*)(gd + 4);
            float4 s0 = *(const float4*)gs;
            float4 s1 = *(const float4*)(gs + 4);
            v[0] = gelu_f(v[0] + d0.x + s0.x);
            v[1] = gelu_f(v[1] + d0.y + s0.y);
            v[2] = gelu_f(v[2] + d0.z + s0.z);
            v[3] = gelu_f(v[3] + d0.w + s0.w);
            v[4] = gelu_f(v[4] + d1.x + s1.x);
            v[5] = gelu_f(v[5] + d1.y + s1.y);
            v[6] = gelu_f(v[6] + d1.z + s1.z);
            v[7] = gelu_f(v[7] + d1.w + s1.w);
        }
        if (EPI == 3) {
            int node = idxD[row];
            float sc = sscale[row];
            float* dp = C + (size_t)node * Ncols + bn + tx * 8;
            red_add_v4(dp,     v[0] * sc, v[1] * sc, v[2] * sc, v[3] * sc);
            red_add_v4(dp + 4, v[4] * sc, v[5] * sc, v[6] * sc, v[7] * sc);
        } else {
            float* cp = C + (size_t)row * Ncols + bn + tx * 8;
            *(float4*)cp       = *(float4*)(v);
            *(float4*)(cp + 4) = *(float4*)(v + 4);
        }
    }
}

// ---------------- small kernels ----------------
__global__ void k_detect(const void* ei) {
    if (blockIdx.x == 0 && threadIdx.x == 0) {
        const long long* p = (const long long*)ei;
        int ok = 1;
        for (int i = 0; i < 64; i++) {
            long long v = p[i];
            if (v < 0 || v >= (long long)Nn) { ok = 0; break; }
        }
        g_is64 = ok;
    }
}

__global__ void k_convert(const void* ei) {
    int i = blockIdx.x * blockDim.x + threadIdx.x;
    if (i >= Ee) return;
    if (g_is64) {
        const long long* p = (const long long*)ei;
        g_src[i] = (int)p[i];
        g_dst[i] = (int)p[Ee + i];
    } else {
        const int* p = (const int*)ei;
        g_src[i] = p[i];
        g_dst[i] = p[Ee + i];
    }
}

__global__ void k_escale(const float* __restrict__ qd, const float* __restrict__ wd,
                         const float* __restrict__ bd) {
    int e = blockIdx.x * blockDim.x + threadIdx.x;
    if (e >= Ee) return;
    float q = qd[e];
    float s = 0.f;
#pragma unroll
    for (int h = 0; h < 4; h++) s += sigm_f(q * wd[h] + bd[h]);
    g_escale[e] = 1.f + 0.25f * s;
}

__global__ void k_zero(float* p, int n) {
    int i = blockIdx.x * blockDim.x + threadIdx.x;
    if (i < n) p[i] = 0.f;
}
__global__ void k_fillu(unsigned* p, int n, unsigned v) {
    int i = blockIdx.x * blockDim.x + threadIdx.x;
    if (i < n) p[i] = v;
}

__global__ void k_pack2(const float* __restrict__ A, const float* __restrict__ B,
                        float* __restrict__ out, int K, int nA, int nB) {
    int i = blockIdx.x * blockDim.x + threadIdx.x;
    int Wt = nA + nB;
    if (i >= K * Wt) return;
    int k = i / Wt, j = i - k * Wt;
    out[i] = (j < nA) ? A[k * nA + j] : B[k * nB + (j - nA)];
}

// one warp per edge: per-head q.k + tanh temporal bias; atomicMax segment max
__global__ void k_scores(const float* __restrict__ tp, const float* __restrict__ wt,
                         const float* __restrict__ bt) {
    int e = blockIdx.x * 8 + (threadIdx.x >> 5);
    if (e >= Ee) return;
    int lane = threadIdx.x & 31;
    int h = lane >> 3, j = lane & 7;
    int dst = g_dst[e];
    float4 q = *(const float4*)(g_Qn + (size_t)dst * 128 + h * 32 + j * 4);
    float4 k = *(const float4*)(g_e256 + (size_t)e * 256 + h * 32 + j * 4);
    float d = q.x * k.x + q.y * k.y + q.z * k.z + q.w * k.w;
    d += __shfl_xor_sync(0xffffffffu, d, 1);
    d += __shfl_xor_sync(0xffffffffu, d, 2);
    d += __shfl_xor_sync(0xffffffffu, d, 4);
    if (j == 0) {
        float s = d * 0.17677669529663687f + tanhf(tp[e] * wt[h] + bt[h]);
        g_scores[(size_t)e * 4 + h] = s;
        atomicMax(&g_smax[dst * 4 + h], fenc(s));
    }
}

__global__ void k_expsum() {
    int i = blockIdx.x * blockDim.x + threadIdx.x;
    if (i >= Ee * 4) return;
    int e = i >> 2, h = i & 3;
    int dst = g_dst[e];
    float mx = fdec(g_smax[dst * 4 + h]);
    float ex = expf(g_scores[i] - mx);
    g_scores[i] = ex;
    atomicAdd(&g_ssum[dst * 4 + h], ex);
}

// one warp per edge: msg = attn*v, scatter red.add into agg
__global__ void k_message() {
    int e = blockIdx.x * 8 + (threadIdx.x >> 5);
    if (e >= Ee) return;
    int lane = threadIdx.x & 31;
    int h = lane >> 3, j = lane & 7;
    int dst = g_dst[e];
    float attn = g_scores[(size_t)e * 4 + h] / g_ssum[dst * 4 + h];
    float4 v = *(const float4*)(g_e256 + (size_t)e * 256 + 128 + h * 32 + j * 4);
    float* o = g_agg + (size_t)dst * 128 + h * 32 + j * 4;
    red_add_v4(o, attn * v.x, attn * v.y, attn * v.z, attn * v.w);
}

// out = LN(a + b), one warp per 128-wide row
__global__ void k_ln_add(const float* __restrict__ a, const float* __restrict__ b,
                         float* __restrict__ out) {
    int n = blockIdx.x * 8 + (threadIdx.x >> 5);
    if (n >= Nn) return;
    int lane = threadIdx.x & 31;
    float4 va = ((const float4*)a)[(size_t)n * 32 + lane];
    float4 vb = ((const float4*)b)[(size_t)n * 32 + lane];
    float4 p = make_float4(va.x + vb.x, va.y + vb.y, va.z + vb.z, va.w + vb.w);
    float s = warp_sum32(p.x + p.y + p.z + p.w);
    float sq = warp_sum32(p.x * p.x + p.y * p.y + p.z * p.z + p.w * p.w);
    float m = s * (1.f / 128.f);
    float var = sq * (1.f / 128.f) - m * m;
    float inv = rsqrtf(var + 1e-5f);
    float4 r = make_float4((p.x - m) * inv, (p.y - m) * inv, (p.z - m) * inv, (p.w - m) * inv);
    ((float4*)out)[(size_t)n * 32 + lane] = r;
}

// stage-B combine: g=sigmoid(GU[:,:128]), u=gelu(GU[:,128:]); h2=LN(h*(1-g)+u*g); hn=LN(h2)
__global__ void k_combine() {
    int n = blockIdx.x * 8 + (threadIdx.x >> 5);
    if (n >= Nn) return;
    int lane = threadIdx.x & 31;
    const float4* GU4 = (const float4*)g_GU;
    float4 gv = GU4[(size_t)n * 64 + lane];
    float4 uv = GU4[(size_t)n * 64 + 32 + lane];
    float4 hv = ((const float4*)g_h)[(size_t)n * 32 + lane];
    float gx = sigm_f(gv.x), gy = sigm_f(gv.y), gz = sigm_f(gv.z), gw = sigm_f(gv.w);
    float ux = gelu_f(uv.x), uy = gelu_f(uv.y), uz = gelu_f(uv.z), uw = gelu_f(uv.w);
    float4 p;
    p.x = hv.x * (1.f - gx) + ux * gx;
    p.y = hv.y * (1.f - gy) + uy * gy;
    p.z = hv.z * (1.f - gz) + uz * gz;
    p.w = hv.w * (1.f - gw) + uw * gw;
    float s = warp_sum32(p.x + p.y + p.z + p.w);
    float sq = warp_sum32(p.x * p.x + p.y * p.y + p.z * p.z + p.w * p.w);
    float m = s * (1.f / 128.f);
    float var = sq * (1.f / 128.f) - m * m;
    float inv = rsqrtf(var + 1e-5f);
    float4 h2 = make_float4((p.x - m) * inv, (p.y - m) * inv, (p.z - m) * inv, (p.w - m) * inv);
    ((float4*)g_h2)[(size_t)n * 32 + lane] = h2;
    float s2 = warp_sum32(h2.x + h2.y + h2.z + h2.w);
    float sq2 = warp_sum32(h2.x * h2.x + h2.y * h2.y + h2.z * h2.z + h2.w * h2.w);
    float m2 = s2 * (1.f / 128.f);
    float var2 = sq2 * (1.f / 128.f) - m2 * m2;
    float inv2 = rsqrtf(var2 + 1e-5f);
    float4 hn = make_float4((h2.x - m2) * inv2, (h2.y - m2) * inv2,
                            (h2.z - m2) * inv2, (h2.w - m2) * inv2);
    ((float4*)g_hn)[(size_t)n * 32 + lane] = hn;
}

// out = LN(h2 + G*hff)
__global__ void k_final(float* __restrict__ out) {
    int n = blockIdx.x * 8 + (threadIdx.x >> 5);
    if (n >= Nn) return;
    int lane = threadIdx.x & 31;
    float4 a = ((const float4*)g_h2)[(size_t)n * 32 + lane];
    float4 g = ((const float4*)g_G)[(size_t)n * 32 + lane];
    float4 f = ((const float4*)g_hff)[(size_t)n * 32 + lane];
    float4 p = make_float4(a.x + g.x * f.x, a.y + g.y * f.y, a.z + g.z * f.z, a.w + g.w * f.w);
    float s = warp_sum32(p.x + p.y + p.z + p.w);
    float sq = warp_sum32(p.x * p.x + p.y * p.y + p.z * p.z + p.w * p.w);
    float m = s * (1.f / 128.f);
    float var = sq * (1.f / 128.f) - m * m;
    float inv = rsqrtf(var + 1e-5f);
    float4 r = make_float4((p.x - m) * inv, (p.y - m) * inv, (p.z - m) * inv, (p.w - m) * inv);
    ((float4*)out)[(size_t)n * 32 + lane] = r;
}

// ---------------- launch ----------------
static inline int cdiv_i(int a, int b) { return (a + b - 1) / b; }

extern "C" void kernel_launch(void* const* d_in, const int* in_sizes, int n_in,
                              void* d_out, int out_size) {
    (void)in_sizes; (void)n_in; (void)out_size;
    const float* x    = (const float*)d_in[0];
    const void*  ei   = d_in[1];
    const float* ge   = (const float*)d_in[2];
    const float* tp   = (const float*)d_in[3];
    const float* qd   = (const float*)d_in[4];
    const float* Wq   = (const float*)d_in[5];  const float* bq   = (const float*)d_in[6];
    const float* Wk   = (const float*)d_in[7];  const float* bk   = (const float*)d_in[8];
    const float* Wv   = (const float*)d_in[9];  const float* bv   = (const float*)d_in[10];
    const float* wt   = (const float*)d_in[11]; const float* bt   = (const float*)d_in[12];
    const float* Wo   = (const float*)d_in[13]; const float* bo   = (const float*)d_in[14];
    const float* Wm1  = (const float*)d_in[15]; const float* bm1  = (const float*)d_in[16];
    const float* Wm2  = (const float*)d_in[17]; const float* bm2  = (const float*)d_in[18];
    const float* wd   = (const float*)d_in[19]; const float* bd   = (const float*)d_in[20];
    const float* Wg   = (const float*)d_in[21]; const float* bg   = (const float*)d_in[22];
    const float* Wu   = (const float*)d_in[23]; const float* bu   = (const float*)d_in[24];
    const float* Wf1  = (const float*)d_in[25]; const float* bf1  = (const float*)d_in[26];
    const float* Wf2  = (const float*)d_in[27]; const float* bf2  = (const float*)d_in[28];
    const float* Wgate= (const float*)d_in[29]; const float* bgate= (const float*)d_in[30];

    void* pv;
    float *p_Qn, *p_XKV, *p_e256, *p_agg, *p_agg2, *p_tmp, *p_h, *p_h2, *p_hn, *p_hff, *p_G;
    float *p_Hd, *p_Hs, *p_GU, *p_F1, *p_Wkv, *p_bkv, *p_Wgu, *p_bgu, *p_ssum, *p_escale;
    unsigned* p_smax; int* p_dst; int* p_src;
    cudaGetSymbolAddress(&pv, g_Qn);     p_Qn    = (float*)pv;
    cudaGetSymbolAddress(&pv, g_XKV);    p_XKV   = (float*)pv;
    cudaGetSymbolAddress(&pv, g_e256);   p_e256  = (float*)pv;
    cudaGetSymbolAddress(&pv, g_agg);    p_agg   = (float*)pv;
    cudaGetSymbolAddress(&pv, g_agg2);   p_agg2  = (float*)pv;
    cudaGetSymbolAddress(&pv, g_tmp);    p_tmp   = (float*)pv;
    cudaGetSymbolAddress(&pv, g_h);      p_h     = (float*)pv;
    cudaGetSymbolAddress(&pv, g_h2);     p_h2    = (float*)pv;
    cudaGetSymbolAddress(&pv, g_hn);     p_hn    = (float*)pv;
    cudaGetSymbolAddress(&pv, g_hff);    p_hff   = (float*)pv;
    cudaGetSymbolAddress(&pv, g_G);      p_G     = (float*)pv;
    cudaGetSymbolAddress(&pv, g_Hd);     p_Hd    = (float*)pv;
    cudaGetSymbolAddress(&pv, g_Hs);     p_Hs    = (float*)pv;
    cudaGetSymbolAddress(&pv, g_GU);     p_GU    = (float*)pv;
    cudaGetSymbolAddress(&pv, g_F1);     p_F1    = (float*)pv;
    cudaGetSymbolAddress(&pv, g_Wkv);    p_Wkv   = (float*)pv;
    cudaGetSymbolAddress(&pv, g_bkv);    p_bkv   = (float*)pv;
    cudaGetSymbolAddress(&pv, g_Wgu);    p_Wgu   = (float*)pv;
    cudaGetSymbolAddress(&pv, g_bgu);    p_bgu   = (float*)pv;
    cudaGetSymbolAddress(&pv, g_ssum);   p_ssum  = (float*)pv;
    cudaGetSymbolAddress(&pv, g_escale); p_escale= (float*)pv;
    cudaGetSymbolAddress(&pv, g_smax);   p_smax  = (unsigned*)pv;
    cudaGetSymbolAddress(&pv, g_dst);    p_dst   = (int*)pv;
    cudaGetSymbolAddress(&pv, g_src);    p_src   = (int*)pv;

    const int TB = 256;
    const float* NUL = nullptr;

    // --- prep ---
    k_detect<<<1, 1>>>(ei);
    k_convert<<<cdiv_i(Ee, TB), TB>>>(ei);
    k_escale<<<cdiv_i(Ee, TB), TB>>>(qd, wd, bd);
    k_zero<<<cdiv_i(Nn * 128, TB), TB>>>(p_agg, Nn * 128);
    k_zero<<<cdiv_i(Nn * 128, TB), TB>>>(p_agg2, Nn * 128);
    k_zero<<<cdiv_i(Nn * 4, TB), TB>>>(p_ssum, Nn * 4);
    k_fillu<<<cdiv_i(Nn * 4, TB), TB>>>(p_smax, Nn * 4, 0x007FFFFFu);  // enc(-inf)
    k_pack2<<<cdiv_i(128 * 256, TB), TB>>>(Wk, Wv, p_Wkv, 128, 128, 128);
    k_pack2<<<cdiv_i(256, TB), TB>>>(bk, bv, p_bkv, 1, 128, 128);
    k_pack2<<<cdiv_i(256 * 256, TB), TB>>>(Wg, Wu, p_Wgu, 256, 128, 128);
    k_pack2<<<cdiv_i(256, TB), TB>>>(bg, bu, p_bgu, 1, 128, 128);

    // --- stage A: causal temporal attention ---
    gemm_k<0, false><<<dim3(cdiv_i(Nn, 128), 1), 256>>>(x, NUL, Wq, bq, p_Qn, Nn, 128, 128,
        nullptr, nullptr, nullptr, nullptr, nullptr);
    gemm_k<0, false><<<dim3(cdiv_i(Nn, 128), 2), 256>>>(x, NUL, p_Wkv, p_bkv, p_XKV, Nn, 128, 256,
        nullptr, nullptr, nullptr, nullptr, nullptr);
    // KV = ge@Wkv + XKV[src]   (fused gather-add epilogue)
    gemm_k<4, false><<<dim3(cdiv_i(Ee, 128), 2), 256>>>(ge, NUL, p_Wkv, nullptr, p_e256, Ee, 128, 256,
        nullptr, p_src, p_XKV, nullptr, nullptr);
    k_scores<<<cdiv_i(Ee, 8), 256>>>(tp, wt, bt);
    k_expsum<<<cdiv_i(Ee * 4, TB), TB>>>();
    k_message<<<cdiv_i(Ee, 8), 256>>>();
    gemm_k<0, false><<<dim3(cdiv_i(Nn, 128), 1), 256>>>(p_agg, NUL, Wo, bo, p_tmp, Nn, 128, 128,
        nullptr, nullptr, nullptr, nullptr, nullptr);
    k_ln_add<<<cdiv_i(Nn, 8), 256>>>(x, p_tmp, p_h);

    // --- stage B: entanglement-aware conv ---
    gemm_k<0, false><<<dim3(cdiv_i(Nn, 128), 2), 256>>>(p_h, NUL, Wm1, nullptr, p_Hd, Nn, 128, 256,
        nullptr, nullptr, nullptr, nullptr, nullptr);
    gemm_k<0, false><<<dim3(cdiv_i(Nn, 128), 2), 256>>>(p_h, NUL, Wm1 + 128 * 256, nullptr, p_Hs, Nn, 128, 256,
        nullptr, nullptr, nullptr, nullptr, nullptr);
    // M1 = gelu(ge@Wm1g + Hd[dst] + Hs[src] + bm1)   (fused epilogue)
    gemm_k<5, false><<<dim3(cdiv_i(Ee, 128), 2), 256>>>(ge, NUL, Wm1 + 256 * 256, bm1, p_e256, Ee, 128, 256,
        p_dst, p_src, p_Hd, p_Hs, nullptr);
    gemm_k<3, false><<<dim3(cdiv_i(Ee, 128), 1), 256>>>(p_e256, NUL, Wm2, bm2, p_agg2, Ee, 256, 128,
        p_dst, nullptr, nullptr, nullptr, p_escale);
    // GU = [h|agg2] @ Wgu + bgu   (split-A, no concat materialization)
    gemm_k<0, true><<<dim3(cdiv_i(Nn, 128), 2), 256>>>(p_h, p_agg2, p_Wgu, p_bgu, p_GU, Nn, 256, 256,
        nullptr, nullptr, nullptr, nullptr, nullptr);
    k_combine<<<cdiv_i(Nn, 8), 256>>>();

    // --- stage C: FF + gated residual ---
    gemm_k<1, false><<<dim3(cdiv_i(Nn, 128), 4), 256>>>(p_hn, NUL, Wf1, bf1, p_F1, Nn, 128, 512,
        nullptr, nullptr, nullptr, nullptr, nullptr);
    gemm_k<0, false><<<dim3(cdiv_i(Nn, 128), 1), 256>>>(p_F1, NUL, Wf2, bf2, p_hff, Nn, 512, 128,
        nullptr, nullptr, nullptr, nullptr, nullptr);
    // G = sigmoid([h2|hff] @ Wgate + bgate)   (split-A)
    gemm_k<2, true><<<dim3(cdiv_i(Nn, 128), 1), 256>>>(p_h2, p_hff, Wgate, bgate, p_G, Nn, 256, 128,
        nullptr, nullptr, nullptr, nullptr, nullptr);
    k_final<<<cdiv_i(Nn, 8), 256>>>((float*)d_out);
}

// round 7
// speedup vs baseline: 1.2678x; 1.0355x over previous
#include <cuda_runtime.h>

// Problem constants (fixed shapes for this dataset)
#define Nn 50000
#define Ee 600000

// ---------------- scratch (static __device__ — no allocation allowed) ----------------
__device__ int      g_is64;
__device__ int      g_src[Ee];
__device__ int      g_dst[Ee];
__device__ float    g_escale[Ee];
__device__ float    g_e256[(size_t)Ee * 256];   // KV (stage A) then M1 (stage B)
__device__ float    g_scores[(size_t)Ee * 4];
__device__ unsigned g_smax[Nn * 4];
__device__ float    g_ssum[Nn * 4];
__device__ float    g_Qn[Nn * 128];
__device__ float    g_XKV[Nn * 256];
__device__ float    g_agg[Nn * 128];
__device__ float    g_agg2[Nn * 128];
__device__ float    g_tmp[Nn * 128];
__device__ float    g_h[Nn * 128];
__device__ float    g_h2[Nn * 128];
__device__ float    g_hn[Nn * 128];
__device__ float    g_hff[Nn * 128];
__device__ float    g_G[Nn * 128];
__device__ float    g_Hd[Nn * 256];
__device__ float    g_Hs[Nn * 256];
__device__ float    g_GU[Nn * 256];
__device__ float    g_F1[Nn * 512];
__device__ float    g_Wkv[128 * 256];
__device__ float    g_bkv[256];
__device__ float    g_Wgu[256 * 256];
__device__ float    g_bgu[256];

// ---------------- helpers ----------------
__device__ __forceinline__ float warp_sum32(float v) {
#pragma unroll
    for (int o = 16; o; o >>= 1) v += __shfl_xor_sync(0xffffffffu, v, o);
    return v;
}
__device__ __forceinline__ float gelu_f(float x) {
    return 0.5f * x * (1.0f + erff(x * 0.7071067811865476f));
}
__device__ __forceinline__ float sigm_f(float x) { return 1.0f / (1.0f + expf(-x)); }
__device__ __forceinline__ unsigned fenc(float f) {
    unsigned u = __float_as_uint(f);
    return (u & 0x80000000u) ? ~u : (u | 0x80000000u);
}
__device__ __forceinline__ float fdec(unsigned e) {
    unsigned u = (e & 0x80000000u) ? (e & 0x7fffffffu) : ~e;
    return __uint_as_float(u);
}
__device__ __forceinline__ void red_add_v4(float* p, float a, float b, float c, float d) {
    asm volatile("red.global.add.v4.f32 [%0], {%1, %2, %3, %4};"
                 :: "l"(p), "f"(a), "f"(b), "f"(c), "f"(d) : "memory");
}
__device__ __forceinline__ void red_add_v2(float* p, float a, float b) {
    asm volatile("red.global.add.v2.f32 [%0], {%1, %2};"
                 :: "l"(p), "f"(a), "f"(b) : "memory");
}
// split fp32 into (hi, lo) tf32 pair: a ≈ hi + lo with ~2^-22 residual
__device__ __forceinline__ float2 tf32split(float a) {
    unsigned hi;
    asm("cvt.rna.tf32.f32 %0, %1;" : "=r"(hi) : "f"(a));
    float hf = __uint_as_float(hi);
    float lo = a - hf;
    unsigned lu;
    asm("cvt.rna.tf32.f32 %0, %1;" : "=r"(lu) : "f"(lo));
    return make_float2(hf, __uint_as_float(lu));
}
__device__ __forceinline__ void mma8(float d[4],
    unsigned a0, unsigned a1, unsigned a2, unsigned a3,
    unsigned b0, unsigned b1) {
    asm volatile(
        "mma.sync.aligned.m16n8k8.row.col.f32.tf32.tf32.f32 "
        "{%0,%1,%2,%3}, {%4,%5,%6,%7}, {%8,%9}, {%0,%1,%2,%3};"
        : "+f"(d[0]), "+f"(d[1]), "+f"(d[2]), "+f"(d[3])
        : "r"(a0), "r"(a1), "r"(a2), "r"(a3), "r"(b0), "r"(b1));
}

// ---------------- 128x128 tensor-core GEMM (tf32 2-split ≈ fp32) ----------------
// C[M,Ncols] = A[M,K] @ W[K,Ncols] (+bias) (+activation/fusion)
// If ASPLIT: A columns [0,128) from A, [128,256) from A2 (both row-stride 128).
// EPI: 0=store, 1=gelu, 2=sigmoid,
//      3=scatter red.add.v2 to C[idxD[row]] scaled by sscale[row]
//      4=add t1[idxS[row]] then store
//      5=gelu(acc + bias + t1[idxD[row]] + t2[idxS[row]]) store
// 256 threads = 8 warps in 2x4 grid; warp tile 64x32; mma m16n8k8.
template <int EPI, bool ASPLIT>
__global__ void __launch_bounds__(256) gemm_t(
    const float* __restrict__ A, const float* __restrict__ A2,
    const float* __restrict__ W,
    const float* __restrict__ bias, float* __restrict__ C,
    int M, int K, int Ncols,
    const int* __restrict__ idxD, const int* __restrict__ idxS,
    const float* __restrict__ t1, const float* __restrict__ t2,
    const float* __restrict__ sscale)
{
    __shared__ float2 As2[16][132];  // [k][m] (hi,lo)
    __shared__ float2 Bs2[16][132];  // [k][n] (hi,lo)
    const int tid = threadIdx.x;
    const int bm = blockIdx.x * 128, bn = blockIdx.y * 128;
    const int lane = tid & 31, warp = tid >> 5;
    const int wm = warp >> 2, wn = warp & 3;       // 2 x 4 warp grid
    const int gid = lane >> 2, tig = lane & 3;

    float D[4][4][4];
#pragma unroll
    for (int i = 0; i < 4; i++)
#pragma unroll
        for (int j = 0; j < 4; j++)
#pragma unroll
            for (int r = 0; r < 4; r++) D[i][j][r] = 0.f;

    const int a_row = tid >> 2;          // 0..63 (+64 on r=1)
    const int a_c4 = (tid & 3) << 2;     // 0,4,8,12
    const int b_k = tid >> 5;            // 0..7 (+8 on r=1)
    const int b_c4 = (tid & 31) << 2;    // 0..124

    for (int kb = 0; kb < K; kb += 16) {
        __syncthreads();
        // --- load A tile 128x16, split, store transposed [k][m] ---
#pragma unroll
        for (int r = 0; r < 2; r++) {
            int row = a_row + 64 * r;
            int arow = bm + row;
            float4 av = make_float4(0.f, 0.f, 0.f, 0.f);
            if (arow < M) {
                int kc = kb + a_c4;
                const float* p;
                if (ASPLIT)
                    p = (kc < 128) ? (A + (size_t)arow * 128 + kc)
                                   : (A2 + (size_t)arow * 128 + (kc - 128));
                else
                    p = A + (size_t)arow * K + kc;
                av = *reinterpret_cast<const float4*>(p);
            }
            As2[a_c4 + 0][row] = tf32split(av.x);
            As2[a_c4 + 1][row] = tf32split(av.y);
            As2[a_c4 + 2][row] = tf32split(av.z);
            As2[a_c4 + 3][row] = tf32split(av.w);
        }
        // --- load B tile 16x128, split, store [k][n] ---
#pragma unroll
        for (int r = 0; r < 2; r++) {
            int krow = b_k + 8 * r;
            float4 bv = *reinterpret_cast<const float4*>(
                W + (size_t)(kb + krow) * Ncols + bn + b_c4);
            Bs2[krow][b_c4 + 0] = tf32split(bv.x);
            Bs2[krow][b_c4 + 1] = tf32split(bv.y);
            Bs2[krow][b_c4 + 2] = tf32split(bv.z);
            Bs2[krow][b_c4 + 3] = tf32split(bv.w);
        }
        __syncthreads();
        // --- two k8 sub-steps ---
#pragma unroll
        for (int ks = 0; ks < 16; ks += 8) {
            float2 af[4][4];
            float2 bf[4][2];
#pragma unroll
            for (int i = 0; i < 4; i++) {
                int m0 = wm * 64 + i * 16;
                af[i][0] = As2[ks + tig][m0 + gid];
                af[i][1] = As2[ks + tig][m0 + gid + 8];
                af[i][2] = As2[ks + tig + 4][m0 + gid];
                af[i][3] = As2[ks + tig + 4][m0 + gid + 8];
            }
#pragma unroll
            for (int j = 0; j < 4; j++) {
                int n0 = wn * 32 + j * 8;
                bf[j][0] = Bs2[ks + tig][n0 + gid];
                bf[j][1] = Bs2[ks + tig + 4][n0 + gid];
            }
#pragma unroll
            for (int i = 0; i < 4; i++) {
                unsigned ah0 = __float_as_uint(af[i][0].x), ah1 = __float_as_uint(af[i][1].x);
                unsigned ah2 = __float_as_uint(af[i][2].x), ah3 = __float_as_uint(af[i][3].x);
                unsigned al0 = __float_as_uint(af[i][0].y), al1 = __float_as_uint(af[i][1].y);
                unsigned al2 = __float_as_uint(af[i][2].y), al3 = __float_as_uint(af[i][3].y);
#pragma unroll
                for (int j = 0; j < 4; j++) {
                    unsigned bh0 = __float_as_uint(bf[j][0].x), bh1 = __float_as_uint(bf[j][1].x);
                    unsigned bl0 = __float_as_uint(bf[j][0].y), bl1 = __float_as_uint(bf[j][1].y);
                    mma8(D[i][j], ah0, ah1, ah2, ah3, bl0, bl1);  // hi*lo
                    mma8(D[i][j], al0, al1, al2, al3, bh0, bh1);  // lo*hi
                    mma8(D[i][j], ah0, ah1, ah2, ah3, bh0, bh1);  // hi*hi
                }
            }
        }
    }

    // ---------------- epilogue ----------------
    const int colb = bn + wn * 32 + 2 * tig;   // + j*8
    float bj[4][2];
#pragma unroll
    for (int j = 0; j < 4; j++) {
        if (bias) {
            float2 t = *reinterpret_cast<const float2*>(bias + colb + j * 8);
            bj[j][0] = t.x; bj[j][1] = t.y;
        } else {
            bj[j][0] = 0.f; bj[j][1] = 0.f;
        }
    }
#pragma unroll
    for (int i = 0; i < 4; i++) {
#pragma unroll
        for (int half = 0; half < 2; half++) {
            int row = bm + wm * 64 + i * 16 + half * 8 + gid;
            if (row >= M) continue;
            float v[4][2];
#pragma unroll
            for (int j = 0; j < 4; j++) {
                v[j][0] = D[i][j][half * 2]     + bj[j][0];
                v[j][1] = D[i][j][half * 2 + 1] + bj[j][1];
            }
            if (EPI == 1) {
#pragma unroll
                for (int j = 0; j < 4; j++) { v[j][0] = gelu_f(v[j][0]); v[j][1] = gelu_f(v[j][1]); }
            }
            if (EPI == 2) {
#pragma unroll
                for (int j = 0; j < 4; j++) { v[j][0] = sigm_f(v[j][0]); v[j][1] = sigm_f(v[j][1]); }
            }
            if (EPI == 4) {
                const float* g = t1 + (size_t)idxS[row] * Ncols + colb;
#pragma unroll
                for (int j = 0; j < 4; j++) {
                    float2 t = *reinterpret_cast<const float2*>(g + j * 8);
                    v[j][0] += t.x; v[j][1] += t.y;
                }
            }
            if (EPI == 5) {
                const float* gd = t1 + (size_t)idxD[row] * Ncols + colb;
                const float* gs = t2 + (size_t)idxS[row] * Ncols + colb;
#pragma unroll
                for (int j = 0; j < 4; j++) {
                    float2 d2 = *reinterpret_cast<const float2*>(gd + j * 8);
                    float2 s2 = *reinterpret_cast<const float2*>(gs + j * 8);
                    v[j][0] = gelu_f(v[j][0] + d2.x + s2.x);
                    v[j][1] = gelu_f(v[j][1] + d2.y + s2.y);
                }
            }
            if (EPI == 3) {
                int node = idxD[row];
                float sc = sscale[row];
                float* dp = C + (size_t)node * Ncols + colb;
#pragma unroll
                for (int j = 0; j < 4; j++)
                    red_add_v2(dp + j * 8, v[j][0] * sc, v[j][1] * sc);
            } else {
                float* cp = C + (size_t)row * Ncols + colb;
#pragma unroll
                for (int j = 0; j < 4; j++)
                    *reinterpret_cast<float2*>(cp + j * 8) = make_float2(v[j][0], v[j][1]);
            }
        }
    }
}

// ---------------- small kernels ----------------
__global__ void k_detect(const void* ei) {
    if (blockIdx.x == 0 && threadIdx.x == 0) {
        const long long* p = (const long long*)ei;
        int ok = 1;
        for (int i = 0; i < 64; i++) {
            long long v = p[i];
            if (v < 0 || v >= (long long)Nn) { ok = 0; break; }
        }
        g_is64 = ok;
    }
}

__global__ void k_convert(const void* ei) {
    int i = blockIdx.x * blockDim.x + threadIdx.x;
    if (i >= Ee) return;
    if (g_is64) {
        const long long* p = (const long long*)ei;
        g_src[i] = (int)p[i];
        g_dst[i] = (int)p[Ee + i];
    } else {
        const int* p = (const int*)ei;
        g_src[i] = p[i];
        g_dst[i] = p[Ee + i];
    }
}

__global__ void k_escale(const float* __restrict__ qd, const float* __restrict__ wd,
                         const float* __restrict__ bd) {
    int e = blockIdx.x * blockDim.x + threadIdx.x;
    if (e >= Ee) return;
    float q = qd[e];
    float s = 0.f;
#pragma unroll
    for (int h = 0; h < 4; h++) s += sigm_f(q * wd[h] + bd[h]);
    g_escale[e] = 1.f + 0.25f * s;
}

__global__ void k_zero(float* p, int n) {
    int i = blockIdx.x * blockDim.x + threadIdx.x;
    if (i < n) p[i] = 0.f;
}
__global__ void k_fillu(unsigned* p, int n, unsigned v) {
    int i = blockIdx.x * blockDim.x + threadIdx.x;
    if (i < n) p[i] = v;
}

__global__ void k_pack2(const float* __restrict__ A, const float* __restrict__ B,
                        float* __restrict__ out, int K, int nA, int nB) {
    int i = blockIdx.x * blockDim.x + threadIdx.x;
    int Wt = nA + nB;
    if (i >= K * Wt) return;
    int k = i / Wt, j = i - k * Wt;
    out[i] = (j < nA) ? A[k * nA + j] : B[k * nB + (j - nA)];
}

// one warp per edge: per-head q.k + tanh temporal bias; atomicMax segment max
__global__ void k_scores(const float* __restrict__ tp, const float* __restrict__ wt,
                         const float* __restrict__ bt) {
    int e = blockIdx.x * 8 + (threadIdx.x >> 5);
    if (e >= Ee) return;
    int lane = threadIdx.x & 31;
    int h = lane >> 3, j = lane & 7;
    int dst = g_dst[e];
    float4 q = *(const float4*)(g_Qn + (size_t)dst * 128 + h * 32 + j * 4);
    float4 k = *(const float4*)(g_e256 + (size_t)e * 256 + h * 32 + j * 4);
    float d = q.x * k.x + q.y * k.y + q.z * k.z + q.w * k.w;
    d += __shfl_xor_sync(0xffffffffu, d, 1);
    d += __shfl_xor_sync(0xffffffffu, d, 2);
    d += __shfl_xor_sync(0xffffffffu, d, 4);
    if (j == 0) {
        float s = d * 0.17677669529663687f + tanhf(tp[e] * wt[h] + bt[h]);
        g_scores[(size_t)e * 4 + h] = s;
        atomicMax(&g_smax[dst * 4 + h], fenc(s));
    }
}

__global__ void k_expsum() {
    int i = blockIdx.x * blockDim.x + threadIdx.x;
    if (i >= Ee * 4) return;
    int e = i >> 2, h = i & 3;
    int dst = g_dst[e];
    float mx = fdec(g_smax[dst * 4 + h]);
    float ex = expf(g_scores[i] - mx);
    g_scores[i] = ex;
    atomicAdd(&g_ssum[dst * 4 + h], ex);
}

// one warp per edge: msg = attn*v, scatter red.add into agg
__global__ void k_message() {
    int e = blockIdx.x * 8 + (threadIdx.x >> 5);
    if (e >= Ee) return;
    int lane = threadIdx.x & 31;
    int h = lane >> 3, j = lane & 7;
    int dst = g_dst[e];
    float attn = g_scores[(size_t)e * 4 + h] / g_ssum[dst * 4 + h];
    float4 v = *(const float4*)(g_e256 + (size_t)e * 256 + 128 + h * 32 + j * 4);
    float* o = g_agg + (size_t)dst * 128 + h * 32 + j * 4;
    red_add_v4(o, attn * v.x, attn * v.y, attn * v.z, attn * v.w);
}

// out = LN(a + b), one warp per 128-wide row
__global__ void k_ln_add(const float* __restrict__ a, const float* __restrict__ b,
                         float* __restrict__ out) {
    int n = blockIdx.x * 8 + (threadIdx.x >> 5);
    if (n >= Nn) return;
    int lane = threadIdx.x & 31;
    float4 va = ((const float4*)a)[(size_t)n * 32 + lane];
    float4 vb = ((const float4*)b)[(size_t)n * 32 + lane];
    float4 p = make_float4(va.x + vb.x, va.y + vb.y, va.z + vb.z, va.w + vb.w);
    float s = warp_sum32(p.x + p.y + p.z + p.w);
    float sq = warp_sum32(p.x * p.x + p.y * p.y + p.z * p.z + p.w * p.w);
    float m = s * (1.f / 128.f);
    float var = sq * (1.f / 128.f) - m * m;
    float inv = rsqrtf(var + 1e-5f);
    float4 r = make_float4((p.x - m) * inv, (p.y - m) * inv, (p.z - m) * inv, (p.w - m) * inv);
    ((float4*)out)[(size_t)n * 32 + lane] = r;
}

// stage-B combine: g=sigmoid(GU[:,:128]), u=gelu(GU[:,128:]); h2=LN(h*(1-g)+u*g); hn=LN(h2)
__global__ void k_combine() {
    int n = blockIdx.x * 8 + (threadIdx.x >> 5);
    if (n >= Nn) return;
    int lane = threadIdx.x & 31;
    const float4* GU4 = (const float4*)g_GU;
    float4 gv = GU4[(size_t)n * 64 + lane];
    float4 uv = GU4[(size_t)n * 64 + 32 + lane];
    float4 hv = ((const float4*)g_h)[(size_t)n * 32 + lane];
    float gx = sigm_f(gv.x), gy = sigm_f(gv.y), gz = sigm_f(gv.z), gw = sigm_f(gv.w);
    float ux = gelu_f(uv.x), uy = gelu_f(uv.y), uz = gelu_f(uv.z), uw = gelu_f(uv.w);
    float4 p;
    p.x = hv.x * (1.f - gx) + ux * gx;
    p.y = hv.y * (1.f - gy) + uy * gy;
    p.z = hv.z * (1.f - gz) + uz * gz;
    p.w = hv.w * (1.f - gw) + uw * gw;
    float s = warp_sum32(p.x + p.y + p.z + p.w);
    float sq = warp_sum32(p.x * p.x + p.y * p.y + p.z * p.z + p.w * p.w);
    float m = s * (1.f / 128.f);
    float var = sq * (1.f / 128.f) - m * m;
    float inv = rsqrtf(var + 1e-5f);
    float4 h2 = make_float4((p.x - m) * inv, (p.y - m) * inv, (p.z - m) * inv, (p.w - m) * inv);
    ((float4*)g_h2)[(size_t)n * 32 + lane] = h2;
    float s2 = warp_sum32(h2.x + h2.y + h2.z + h2.w);
    float sq2 = warp_sum32(h2.x * h2.x + h2.y * h2.y + h2.z * h2.z + h2.w * h2.w);
    float m2 = s2 * (1.f / 128.f);
    float var2 = sq2 * (1.f / 128.f) - m2 * m2;
    float inv2 = rsqrtf(var2 + 1e-5f);
    float4 hn = make_float4((h2.x - m2) * inv2, (h2.y - m2) * inv2,
                            (h2.z - m2) * inv2, (h2.w - m2) * inv2);
    ((float4*)g_hn)[(size_t)n * 32 + lane] = hn;
}

// out = LN(h2 + G*hff)
__global__ void k_final(float* __restrict__ out) {
    int n = blockIdx.x * 8 + (threadIdx.x >> 5);
    if (n >= Nn) return;
    int lane = threadIdx.x & 31;
    float4 a = ((const float4*)g_h2)[(size_t)n * 32 + lane];
    float4 g = ((const float4*)g_G)[(size_t)n * 32 + lane];
    float4 f = ((const float4*)g_hff)[(size_t)n * 32 + lane];
    float4 p = make_float4(a.x + g.x * f.x, a.y + g.y * f.y, a.z + g.z * f.z, a.w + g.w * f.w);
    float s = warp_sum32(p.x + p.y + p.z + p.w);
    float sq = warp_sum32(p.x * p.x + p.y * p.y + p.z * p.z + p.w * p.w);
    float m = s * (1.f / 128.f);
    float var = sq * (1.f / 128.f) - m * m;
    float inv = rsqrtf(var + 1e-5f);
    float4 r = make_float4((p.x - m) * inv, (p.y - m) * inv, (p.z - m) * inv, (p.w - m) * inv);
    ((float4*)out)[(size_t)n * 32 + lane] = r;
}

// ---------------- launch ----------------
static inline int cdiv_i(int a, int b) { return (a + b - 1) / b; }

extern "C" void kernel_launch(void* const* d_in, const int* in_sizes, int n_in,
                              void* d_out, int out_size) {
    (void)in_sizes; (void)n_in; (void)out_size;
    const float* x    = (const float*)d_in[0];
    const void*  ei   = d_in[1];
    const float* ge   = (const float*)d_in[2];
    const float* tp   = (const float*)d_in[3];
    const float* qd   = (const float*)d_in[4];
    const float* Wq   = (const float*)d_in[5];  const float* bq   = (const float*)d_in[6];
    const float* Wk   = (const float*)d_in[7];  const float* bk   = (const float*)d_in[8];
    const float* Wv   = (const float*)d_in[9];  const float* bv   = (const float*)d_in[10];
    const float* wt   = (const float*)d_in[11]; const float* bt   = (const float*)d_in[12];
    const float* Wo   = (const float*)d_in[13]; const float* bo   = (const float*)d_in[14];
    const float* Wm1  = (const float*)d_in[15]; const float* bm1  = (const float*)d_in[16];
    const float* Wm2  = (const float*)d_in[17]; const float* bm2  = (const float*)d_in[18];
    const float* wd   = (const float*)d_in[19]; const float* bd   = (const float*)d_in[20];
    const float* Wg   = (const float*)d_in[21]; const float* bg   = (const float*)d_in[22];
    const float* Wu   = (const float*)d_in[23]; const float* bu   = (const float*)d_in[24];
    const float* Wf1  = (const float*)d_in[25]; const float* bf1  = (const float*)d_in[26];
    const float* Wf2  = (const float*)d_in[27]; const float* bf2  = (const float*)d_in[28];
    const float* Wgate= (const float*)d_in[29]; const float* bgate= (const float*)d_in[30];

    void* pv;
    float *p_Qn, *p_XKV, *p_e256, *p_agg, *p_agg2, *p_tmp, *p_h, *p_h2, *p_hn, *p_hff, *p_G;
    float *p_Hd, *p_Hs, *p_GU, *p_F1, *p_Wkv, *p_bkv, *p_Wgu, *p_bgu, *p_ssum, *p_escale;
    unsigned* p_smax; int* p_dst; int* p_src;
    cudaGetSymbolAddress(&pv, g_Qn);     p_Qn    = (float*)pv;
    cudaGetSymbolAddress(&pv, g_XKV);    p_XKV   = (float*)pv;
    cudaGetSymbolAddress(&pv, g_e256);   p_e256  = (float*)pv;
    cudaGetSymbolAddress(&pv, g_agg);    p_agg   = (float*)pv;
    cudaGetSymbolAddress(&pv, g_agg2);   p_agg2  = (float*)pv;
    cudaGetSymbolAddress(&pv, g_tmp);    p_tmp   = (float*)pv;
    cudaGetSymbolAddress(&pv, g_h);      p_h     = (float*)pv;
    cudaGetSymbolAddress(&pv, g_h2);     p_h2    = (float*)pv;
    cudaGetSymbolAddress(&pv, g_hn);     p_hn    = (float*)pv;
    cudaGetSymbolAddress(&pv, g_hff);    p_hff   = (float*)pv;
    cudaGetSymbolAddress(&pv, g_G);      p_G     = (float*)pv;
    cudaGetSymbolAddress(&pv, g_Hd);     p_Hd    = (float*)pv;
    cudaGetSymbolAddress(&pv, g_Hs);     p_Hs    = (float*)pv;
    cudaGetSymbolAddress(&pv, g_GU);     p_GU    = (float*)pv;
    cudaGetSymbolAddress(&pv, g_F1);     p_F1    = (float*)pv;
    cudaGetSymbolAddress(&pv, g_Wkv);    p_Wkv   = (float*)pv;
    cudaGetSymbolAddress(&pv, g_bkv);    p_bkv   = (float*)pv;
    cudaGetSymbolAddress(&pv, g_Wgu);    p_Wgu   = (float*)pv;
    cudaGetSymbolAddress(&pv, g_bgu);    p_bgu   = (float*)pv;
    cudaGetSymbolAddress(&pv, g_ssum);   p_ssum  = (float*)pv;
    cudaGetSymbolAddress(&pv, g_escale); p_escale= (float*)pv;
    cudaGetSymbolAddress(&pv, g_smax);   p_smax  = (unsigned*)pv;
    cudaGetSymbolAddress(&pv, g_dst);    p_dst   = (int*)pv;
    cudaGetSymbolAddress(&pv, g_src);    p_src   = (int*)pv;

    const int TB = 256;
    const float* NUL = nullptr;

    // --- prep ---
    k_detect<<<1, 1>>>(ei);
    k_convert<<<cdiv_i(Ee, TB), TB>>>(ei);
    k_escale<<<cdiv_i(Ee, TB), TB>>>(qd, wd, bd);
    k_zero<<<cdiv_i(Nn * 128, TB), TB>>>(p_agg, Nn * 128);
    k_zero<<<cdiv_i(Nn * 128, TB), TB>>>(p_agg2, Nn * 128);
    k_zero<<<cdiv_i(Nn * 4, TB), TB>>>(p_ssum, Nn * 4);
    k_fillu<<<cdiv_i(Nn * 4, TB), TB>>>(p_smax, Nn * 4, 0x007FFFFFu);  // enc(-inf)
    k_pack2<<<cdiv_i(128 * 256, TB), TB>>>(Wk, Wv, p_Wkv, 128, 128, 128);
    k_pack2<<<cdiv_i(256, TB), TB>>>(bk, bv, p_bkv, 1, 128, 128);
    k_pack2<<<cdiv_i(256 * 256, TB), TB>>>(Wg, Wu, p_Wgu, 256, 128, 128);
    k_pack2<<<cdiv_i(256, TB), TB>>>(bg, bu, p_bgu, 1, 128, 128);

    // --- stage A: causal temporal attention ---
    gemm_t<0, false><<<dim3(cdiv_i(Nn, 128), 1), 256>>>(x, NUL, Wq, bq, p_Qn, Nn, 128, 128,
        nullptr, nullptr, nullptr, nullptr, nullptr);
    gemm_t<0, false><<<dim3(cdiv_i(Nn, 128), 2), 256>>>(x, NUL, p_Wkv, p_bkv, p_XKV, Nn, 128, 256,
        nullptr, nullptr, nullptr, nullptr, nullptr);
    // KV = ge@Wkv + XKV[src]   (fused gather-add epilogue)
    gemm_t<4, false><<<dim3(cdiv_i(Ee, 128), 2), 256>>>(ge, NUL, p_Wkv, nullptr, p_e256, Ee, 128, 256,
        nullptr, p_src, p_XKV, nullptr, nullptr);
    k_scores<<<cdiv_i(Ee, 8), 256>>>(tp, wt, bt);
    k_expsum<<<cdiv_i(Ee * 4, TB), TB>>>();
    k_message<<<cdiv_i(Ee, 8), 256>>>();
    gemm_t<0, false><<<dim3(cdiv_i(Nn, 128), 1), 256>>>(p_agg, NUL, Wo, bo, p_tmp, Nn, 128, 128,
        nullptr, nullptr, nullptr, nullptr, nullptr);
    k_ln_add<<<cdiv_i(Nn, 8), 256>>>(x, p_tmp, p_h);

    // --- stage B: entanglement-aware conv ---
    gemm_t<0, false><<<dim3(cdiv_i(Nn, 128), 2), 256>>>(p_h, NUL, Wm1, nullptr, p_Hd, Nn, 128, 256,
        nullptr, nullptr, nullptr, nullptr, nullptr);
    gemm_t<0, false><<<dim3(cdiv_i(Nn, 128), 2), 256>>>(p_h, NUL, Wm1 + 128 * 256, nullptr, p_Hs, Nn, 128, 256,
        nullptr, nullptr, nullptr, nullptr, nullptr);
    // M1 = gelu(ge@Wm1g + Hd[dst] + Hs[src] + bm1)   (fused epilogue)
    gemm_t<5, false><<<dim3(cdiv_i(Ee, 128), 2), 256>>>(ge, NUL, Wm1 + 256 * 256, bm1, p_e256, Ee, 128, 256,
        p_dst, p_src, p_Hd, p_Hs, nullptr);
    gemm_t<3, false><<<dim3(cdiv_i(Ee, 128), 1), 256>>>(p_e256, NUL, Wm2, bm2, p_agg2, Ee, 256, 128,
        p_dst, nullptr, nullptr, nullptr, p_escale);
    // GU = [h|agg2] @ Wgu + bgu   (split-A, no concat materialization)
    gemm_t<0, true><<<dim3(cdiv_i(Nn, 128), 2), 256>>>(p_h, p_agg2, p_Wgu, p_bgu, p_GU, Nn, 256, 256,
        nullptr, nullptr, nullptr, nullptr, nullptr);
    k_combine<<<cdiv_i(Nn, 8), 256>>>();

    // --- stage C: FF + gated residual ---
    gemm_t<1, false><<<dim3(cdiv_i(Nn, 128), 4), 256>>>(p_hn, NUL, Wf1, bf1, p_F1, Nn, 128, 512,
        nullptr, nullptr, nullptr, nullptr, nullptr);
    gemm_t<0, false><<<dim3(cdiv_i(Nn, 128), 1), 256>>>(p_F1, NUL, Wf2, bf2, p_hff, Nn, 512, 128,
        nullptr, nullptr, nullptr, nullptr, nullptr);
    // G = sigmoid([h2|hff] @ Wgate + bgate)   (split-A)
    gemm_t<2, true><<<dim3(cdiv_i(Nn, 128), 1), 256>>>(p_h2, p_hff, Wgate, bgate, p_G, Nn, 256, 128,
        nullptr, nullptr, nullptr, nullptr, nullptr);
    k_final<<<cdiv_i(Nn, 8), 256>>>((float*)d_out);
}